// round 6
// baseline (speedup 1.0000x reference)
#include <cuda_runtime.h>
#include <math.h>
#include <stdint.h>

#define BATCH 8192
#define KDIM  1024
#define HDIM  1024
#define FH    4096

// Scratch: raw gate pre-activations + tf32-prerounded operand copies.
__device__ float g_ig[(size_t)BATCH * FH];
__device__ float g_hg[(size_t)BATCH * FH];
__device__ float g_A [(size_t)BATCH * KDIM];
__device__ float g_H [(size_t)BATCH * KDIM];
__device__ float g_Wi[(size_t)FH * KDIM];
__device__ float g_Wh[(size_t)FH * KDIM];

// ---------------------------------------------------------------------------
// tf32 pre-rounding (RNA), all 4 tensors in one launch (blockIdx.y selects).
// ---------------------------------------------------------------------------
__device__ __forceinline__ float to_tf32(float x) {
    uint32_t u;
    asm("cvt.rna.tf32.f32 %0, %1;" : "=r"(u) : "f"(x));
    return __uint_as_float(u);
}

__global__ void __launch_bounds__(256)
round_all_kernel(const float* __restrict__ s0, const float* __restrict__ s1,
                 const float* __restrict__ s2, const float* __restrict__ s3,
                 float* __restrict__ d0, float* __restrict__ d1,
                 float* __restrict__ d2, float* __restrict__ d3)
{
    const float* src; float* dst; int n4;
    switch (blockIdx.y) {
        case 0: src = s0; dst = d0; n4 = (BATCH * KDIM) / 4; break;
        case 1: src = s1; dst = d1; n4 = (BATCH * KDIM) / 4; break;
        case 2: src = s2; dst = d2; n4 = (FH * KDIM) / 4; break;
        default: src = s3; dst = d3; n4 = (FH * KDIM) / 4; break;
    }
    int i = blockIdx.x * blockDim.x + threadIdx.x;
    int stride = gridDim.x * blockDim.x;
    for (; i < n4; i += stride) {
        float4 v = ((const float4*)src)[i];
        v.x = to_tf32(v.x); v.y = to_tf32(v.y);
        v.z = to_tf32(v.z); v.w = to_tf32(v.w);
        ((float4*)dst)[i] = v;
    }
}

// ---------------------------------------------------------------------------
// GEMM: out[m,n] = sum_k A[m,k] * W[n,k]  (mma.sync tf32 + ldmatrix + cp.async)
// CTA tile 128x256x64, 2 stages, 16 warps (4x4), warp tile 32x64.
// ---------------------------------------------------------------------------
#define BM 128
#define BN 256
#define BK 64
#define NCHUNK (KDIM / BK)                 // 16
#define ROWW  (BK + 4)                     // 68 floats per smem row
#define A_BYTES (BM * ROWW * 4)            // 34816
#define B_BYTES (BN * ROWW * 4)            // 69632
#define STAGE_BYTES (A_BYTES + B_BYTES)    // 104448
#define SMEM_TOTAL (2 * STAGE_BYTES)       // 208896
#define NTHREADS 512

__device__ __forceinline__ uint32_t smem_u32(const void* p) {
    uint32_t a;
    asm("{ .reg .u64 t; cvta.to.shared.u64 t, %1; cvt.u32.u64 %0, t; }" : "=r"(a) : "l"(p));
    return a;
}

__device__ __forceinline__ void cp16(uint32_t saddr, const void* g) {
    asm volatile("cp.async.cg.shared.global [%0], [%1], 16;" :: "r"(saddr), "l"(g));
}
#define CP_COMMIT() asm volatile("cp.async.commit_group;" ::: "memory")
#define CP_WAIT_1() asm volatile("cp.async.wait_group 1;" ::: "memory")

__device__ __forceinline__ void ldsm4(uint32_t& r0, uint32_t& r1, uint32_t& r2, uint32_t& r3,
                                      uint32_t addr) {
    asm volatile("ldmatrix.sync.aligned.m8n8.x4.shared.b16 {%0,%1,%2,%3}, [%4];"
                 : "=r"(r0), "=r"(r1), "=r"(r2), "=r"(r3) : "r"(addr));
}

__device__ __forceinline__ void mma_tf32(float c[4], const uint32_t a[4], const uint32_t b[2]) {
    asm volatile(
        "mma.sync.aligned.m16n8k8.row.col.f32.tf32.tf32.f32 "
        "{%0,%1,%2,%3}, {%4,%5,%6,%7}, {%8,%9}, {%0,%1,%2,%3};"
        : "+f"(c[0]), "+f"(c[1]), "+f"(c[2]), "+f"(c[3])
        : "r"(a[0]), "r"(a[1]), "r"(a[2]), "r"(a[3]),
          "r"(b[0]), "r"(b[1]));
}

__global__ void __launch_bounds__(NTHREADS, 1)
gemm_tc_kernel(const float* __restrict__ A, const float* __restrict__ W,
               float* __restrict__ out)
{
    extern __shared__ char smem[];
    const uint32_t sbase = smem_u32(smem);

    const int tid  = threadIdx.x;
    const int wid  = tid >> 5;
    const int lane = tid & 31;
    const int wm   = wid >> 2;     // 0..3 -> 32-row slab
    const int wn   = wid & 3;      // 0..3 -> 64-col slab
    const int m0   = blockIdx.y * BM;
    const int n0   = blockIdx.x * BN;

    // cp.async loader: 16 float4 chunks per row; 512 threads
    const int ldrow = tid >> 4;    // 0..31
    const int ldc4  = tid & 15;

    auto load_stage = [&](int st, int c) {
        const uint32_t sA = sbase + st * STAGE_BYTES;
        const uint32_t sB = sA + A_BYTES;
        const int kt = c * BK;
        #pragma unroll
        for (int i = 0; i < 4; i++) {               // A: 128 rows
            int row = ldrow + i * 32;
            cp16(sA + (row * ROWW + ldc4 * 4) * 4,
                 &A[(size_t)(m0 + row) * KDIM + kt + ldc4 * 4]);
        }
        #pragma unroll
        for (int i = 0; i < 8; i++) {               // B: 256 rows
            int row = ldrow + i * 32;
            cp16(sB + (row * ROWW + ldc4 * 4) * 4,
                 &W[(size_t)(n0 + row) * KDIM + kt + ldc4 * 4]);
        }
    };

    // ldmatrix per-lane base offsets (bytes within a stage)
    const int lt  = lane >> 3;      // matrix index 0..3
    const int lri = lane & 7;       // row within matrix
    uint32_t offA[2];
    {
        int row = wm * 32 + lri + (lt & 1) * 8;
        int col = (lt >> 1) * 4;
        #pragma unroll
        for (int mt = 0; mt < 2; mt++)
            offA[mt] = ((row + mt * 16) * ROWW + col) * 4;
    }
    uint32_t offB[4];
    {
        int row = wn * 64 + lri + (lt >> 1) * 8;
        int col = (lt & 1) * 4;
        #pragma unroll
        for (int nt2 = 0; nt2 < 4; nt2++)
            offB[nt2] = (uint32_t)A_BYTES + ((row + nt2 * 16) * ROWW + col) * 4;
    }

    float acc[2][8][4];
    #pragma unroll
    for (int mt = 0; mt < 2; mt++)
        #pragma unroll
        for (int nt = 0; nt < 8; nt++)
            #pragma unroll
            for (int r = 0; r < 4; r++)
                acc[mt][nt][r] = 0.f;

    load_stage(0, 0); CP_COMMIT();
    load_stage(1, 1); CP_COMMIT();

    for (int c = 0; c < NCHUNK; c++) {
        CP_WAIT_1();
        __syncthreads();

        const uint32_t sb = sbase + (c & 1) * STAGE_BYTES;

        #pragma unroll
        for (int kk = 0; kk < BK; kk += 8) {
            const uint32_t kb = kk * 4;
            uint32_t af[2][4];
            #pragma unroll
            for (int mt = 0; mt < 2; mt++)
                ldsm4(af[mt][0], af[mt][1], af[mt][2], af[mt][3], sb + offA[mt] + kb);
            uint32_t bf[8][2];
            #pragma unroll
            for (int nt2 = 0; nt2 < 4; nt2++)
                ldsm4(bf[2*nt2][0], bf[2*nt2][1], bf[2*nt2+1][0], bf[2*nt2+1][1],
                      sb + offB[nt2] + kb);
            #pragma unroll
            for (int mt = 0; mt < 2; mt++)
                #pragma unroll
                for (int nt = 0; nt < 8; nt++)
                    mma_tf32(acc[mt][nt], af[mt], bf[nt]);
        }

        __syncthreads();
        if (c + 2 < NCHUNK) load_stage(c & 1, c + 2);
        CP_COMMIT();
    }

    // epilogue
    #pragma unroll
    for (int mt = 0; mt < 2; mt++) {
        int row0 = m0 + wm * 32 + mt * 16 + (lane >> 2);
        #pragma unroll
        for (int nt = 0; nt < 8; nt++) {
            int col0 = n0 + wn * 64 + nt * 8 + 2 * (lane & 3);
            *(float2*)&out[(size_t)row0 * FH + col0] =
                make_float2(acc[mt][nt][0], acc[mt][nt][1]);
            *(float2*)&out[(size_t)(row0 + 8) * FH + col0] =
                make_float2(acc[mt][nt][2], acc[mt][nt][3]);
        }
    }
}

// ---------------------------------------------------------------------------
// Fused LayerNorm + LSTM gates + cell LayerNorm. float4 path.
// ---------------------------------------------------------------------------
__device__ __forceinline__ float sigmoidf_(float x) {
    return 1.f / (1.f + expf(-x));
}

__device__ __forceinline__ float2 block_sum2(float2 v, float2* sh) {
    #pragma unroll
    for (int o = 16; o > 0; o >>= 1) {
        v.x += __shfl_down_sync(0xffffffffu, v.x, o);
        v.y += __shfl_down_sync(0xffffffffu, v.y, o);
    }
    int lane = threadIdx.x & 31, w = threadIdx.x >> 5;
    if (lane == 0) sh[w] = v;
    __syncthreads();
    if (w == 0) {
        float2 t = (lane < 8) ? sh[lane] : make_float2(0.f, 0.f);
        #pragma unroll
        for (int o = 4; o > 0; o >>= 1) {
            t.x += __shfl_down_sync(0xffffffffu, t.x, o);
            t.y += __shfl_down_sync(0xffffffffu, t.y, o);
        }
        if (lane == 0) sh[0] = t;
    }
    __syncthreads();
    return sh[0];
}

__global__ void __launch_bounds__(256)
fuse_kernel(const float* __restrict__ cx,
            const float* __restrict__ ln_i_w, const float* __restrict__ ln_i_b,
            const float* __restrict__ ln_h_w, const float* __restrict__ ln_h_b,
            const float* __restrict__ ln_c_w, const float* __restrict__ ln_c_b,
            float* __restrict__ out)
{
    const int b   = blockIdx.x;
    const int tid = threadIdx.x;
    const float4* ig4 = (const float4*)(g_ig + (size_t)b * FH);
    const float4* hg4 = (const float4*)(g_hg + (size_t)b * FH);

    __shared__ float4 gates4[FH / 4];
    __shared__ float2 red_i[8], red_h[8], red_c[8];

    float4 vi[4], vh[4];
    float2 si = make_float2(0.f, 0.f), sh_ = make_float2(0.f, 0.f);
    #pragma unroll
    for (int p = 0; p < 4; p++) {
        int j = tid + p * 256;
        float4 a = ig4[j], c = hg4[j];
        vi[p] = a; vh[p] = c;
        si.x += a.x + a.y + a.z + a.w;
        si.y += a.x*a.x + a.y*a.y + a.z*a.z + a.w*a.w;
        sh_.x += c.x + c.y + c.z + c.w;
        sh_.y += c.x*c.x + c.y*c.y + c.z*c.z + c.w*c.w;
    }
    float2 ri = block_sum2(si, red_i);
    float2 rh = block_sum2(sh_, red_h);

    const float inv_fh = 1.f / (float)FH;
    float mu_i = ri.x * inv_fh;
    float rs_i = rsqrtf(ri.y * inv_fh - mu_i * mu_i + 1e-5f);
    float mu_h = rh.x * inv_fh;
    float rs_h = rsqrtf(rh.y * inv_fh - mu_h * mu_h + 1e-5f);

    #pragma unroll
    for (int p = 0; p < 4; p++) {
        int j = tid + p * 256;
        float4 wi = ((const float4*)ln_i_w)[j], bi = ((const float4*)ln_i_b)[j];
        float4 wh = ((const float4*)ln_h_w)[j], bh = ((const float4*)ln_h_b)[j];
        float4 a = vi[p], c = vh[p], g;
        g.x = (a.x - mu_i) * rs_i * wi.x + bi.x + (c.x - mu_h) * rs_h * wh.x + bh.x;
        g.y = (a.y - mu_i) * rs_i * wi.y + bi.y + (c.y - mu_h) * rs_h * wh.y + bh.y;
        g.z = (a.z - mu_i) * rs_i * wi.z + bi.z + (c.z - mu_h) * rs_h * wh.z + bh.z;
        g.w = (a.w - mu_i) * rs_i * wi.w + bi.w + (c.w - mu_h) * rs_h * wh.w + bh.w;
        gates4[j] = g;
    }
    __syncthreads();

    float4 gi = gates4[tid];
    float4 gf = gates4[256 + tid];
    float4 gg = gates4[512 + tid];
    float4 go = gates4[768 + tid];
    float4 c4 = ((const float4*)cx)[b * 256 + tid];

    float4 cv;
    cv.x = sigmoidf_(gf.x) * c4.x + sigmoidf_(gi.x) * tanhf(gg.x);
    cv.y = sigmoidf_(gf.y) * c4.y + sigmoidf_(gi.y) * tanhf(gg.y);
    cv.z = sigmoidf_(gf.z) * c4.z + sigmoidf_(gi.z) * tanhf(gg.z);
    cv.w = sigmoidf_(gf.w) * c4.w + sigmoidf_(gi.w) * tanhf(gg.w);

    float2 sc = make_float2(cv.x + cv.y + cv.z + cv.w,
                            cv.x*cv.x + cv.y*cv.y + cv.z*cv.z + cv.w*cv.w);
    float2 rc = block_sum2(sc, red_c);
    const float inv_h = 1.f / (float)HDIM;
    float mu_c = rc.x * inv_h;
    float rs_c = rsqrtf(rc.y * inv_h - mu_c * mu_c + 1e-5f);

    float4 wc = ((const float4*)ln_c_w)[tid], bc = ((const float4*)ln_c_b)[tid];
    float4 cy, hy;
    cy.x = (cv.x - mu_c) * rs_c * wc.x + bc.x;  hy.x = sigmoidf_(go.x) * tanhf(cy.x);
    cy.y = (cv.y - mu_c) * rs_c * wc.y + bc.y;  hy.y = sigmoidf_(go.y) * tanhf(cy.y);
    cy.z = (cv.z - mu_c) * rs_c * wc.z + bc.z;  hy.z = sigmoidf_(go.z) * tanhf(cy.z);
    cy.w = (cv.w - mu_c) * rs_c * wc.w + bc.w;  hy.w = sigmoidf_(go.w) * tanhf(cy.w);

    ((float4*)out)[(size_t)b * 256 + tid] = hy;
    ((float4*)out)[(size_t)BATCH * 256 + (size_t)b * 256 + tid] = cy;
}

// ---------------------------------------------------------------------------
extern "C" void kernel_launch(void* const* d_in, const int* in_sizes, int n_in,
                              void* d_out, int out_size)
{
    const float* input  = (const float*)d_in[0];
    const float* hx     = (const float*)d_in[1];
    const float* cx     = (const float*)d_in[2];
    const float* wih    = (const float*)d_in[3];
    const float* whh    = (const float*)d_in[4];
    const float* ln_i_w = (const float*)d_in[5];
    const float* ln_i_b = (const float*)d_in[6];
    const float* ln_h_w = (const float*)d_in[7];
    const float* ln_h_b = (const float*)d_in[8];
    const float* ln_c_w = (const float*)d_in[9];
    const float* ln_c_b = (const float*)d_in[10];
    float* out = (float*)d_out;

    cudaFuncSetAttribute(gemm_tc_kernel,
                         cudaFuncAttributeMaxDynamicSharedMemorySize, SMEM_TOTAL);

    float *dA, *dH, *dWi, *dWh, *dIG, *dHG;
    cudaGetSymbolAddress((void**)&dA,  g_A);
    cudaGetSymbolAddress((void**)&dH,  g_H);
    cudaGetSymbolAddress((void**)&dWi, g_Wi);
    cudaGetSymbolAddress((void**)&dWh, g_Wh);
    cudaGetSymbolAddress((void**)&dIG, g_ig);
    cudaGetSymbolAddress((void**)&dHG, g_hg);

    round_all_kernel<<<dim3(160, 4), 256>>>(input, hx, wih, whh, dA, dH, dWi, dWh);

    dim3 grid(FH / BN, BATCH / BM);
    gemm_tc_kernel<<<grid, NTHREADS, SMEM_TOTAL>>>(dA, dWi, dIG);
    gemm_tc_kernel<<<grid, NTHREADS, SMEM_TOTAL>>>(dH, dWh, dHG);
    fuse_kernel<<<BATCH, 256>>>(cx, ln_i_w, ln_i_b, ln_h_w, ln_h_b, ln_c_w, ln_c_b, out);
}